// round 9
// baseline (speedup 1.0000x reference)
#include <cuda_runtime.h>
#include <math.h>
#include <stdint.h>

// Problem constants: B=4, L=2048, HS=2048, NH=32, HD=64, K=16, NM=128, M=B*L=8192

__device__ float g_Q[8192 * 2048];
__device__ float g_K[8192 * 2048];
__device__ float g_V[8192 * 2048];
__device__ float g_Y[8192 * 2048];
__device__ float g_LR[8192 * 32];
__device__ float g_Hr[8192 * 2048];
__device__ float g_Wq[2048 * 2048];
__device__ float g_Wk[2048 * 2048];
__device__ float g_Wv[2048 * 2048];
__device__ float g_Wo[2048 * 2048];

// ---------------------------------------------------------------------------
__device__ __forceinline__ uint32_t f2tf(float x) {
    uint32_t r;
    asm("cvt.rna.tf32.f32 %0, %1;" : "=r"(r) : "f"(x));
    return r;
}

__device__ __forceinline__ void mma_tf32(float* c, const uint32_t* a, const uint32_t* b) {
    asm volatile(
        "mma.sync.aligned.m16n8k8.row.col.f32.tf32.tf32.f32 "
        "{%0,%1,%2,%3}, {%4,%5,%6,%7}, {%8,%9}, {%0,%1,%2,%3};"
        : "+f"(c[0]), "+f"(c[1]), "+f"(c[2]), "+f"(c[3])
        : "r"(a[0]), "r"(a[1]), "r"(a[2]), "r"(a[3]), "r"(b[0]), "r"(b[1]));
}

__device__ __forceinline__ uint32_t smem_u32(const void* p) {
    uint32_t a;
    asm("{ .reg .u64 t; cvta.to.shared.u64 t, %1; cvt.u32.u64 %0, t; }" : "=r"(a) : "l"(p));
    return a;
}

__device__ __forceinline__ void cp16(uint32_t s, const float* g) {
    asm volatile("cp.async.cg.shared.global [%0], [%1], 16;" :: "r"(s), "l"(g));
}
#define CP_COMMIT() asm volatile("cp.async.commit_group;" ::: "memory")
#define CP_WAIT2()  asm volatile("cp.async.wait_group 2;" ::: "memory")

// ---------------------------------------------------------------------------
// tf32 rounding kernel (float4 elementwise)
// ---------------------------------------------------------------------------
__global__ void round_tf32_kernel(const float* __restrict__ in, float* __restrict__ out, int n4)
{
    int i = blockIdx.x * blockDim.x + threadIdx.x;
    if (i < n4) {
        float4 v = ((const float4*)in)[i];
        v.x = __uint_as_float(f2tf(v.x));
        v.y = __uint_as_float(f2tf(v.y));
        v.z = __uint_as_float(f2tf(v.z));
        v.w = __uint_as_float(f2tf(v.w));
        ((float4*)out)[i] = v;
    }
}

// ---------------------------------------------------------------------------
// TF32 tensor-core GEMM: 128x256 CTA tile, 8 warps of 64x64, BK=16,
// 4-stage cp.async pipeline. C[m,n] = sum_k A[m,k]*W[n,k]; inputs
// pre-rounded to tf32 values. Smem [m][k], row stride 20 floats:
// fragment LDS bank = (20*row + tig + k8) mod 32, all 32 lanes distinct.
// ---------------------------------------------------------------------------
#define ST 20
#define A_F (128 * ST)             // floats per A stage
#define B_F (256 * ST)             // floats per B stage
#define STAGE_F (A_F + B_F)        // 7680 floats per stage
#define GEMM_SMEM (4 * STAGE_F * 4)  // 122880 bytes

__global__ __launch_bounds__(256, 1) void gemm_tf32_nt(
    const float* __restrict__ A, const float* __restrict__ W,
    float* __restrict__ C)
{
    extern __shared__ __align__(16) float smem[];

    int tid = threadIdx.x;
    int bm = blockIdx.y * 128, bn = blockIdx.x * 256;
    int warp = tid >> 5, lane = tid & 31;
    int gid = lane >> 2, tig = lane & 3;
    int wm = (warp & 1) * 64, wn = (warp >> 1) * 64;

    // loaders: A row tid>>1 (2 cp16 = 8 floats at lk), B row tid (4 cp16 = 16 floats)
    int lrowA = tid >> 1, lkA = (tid & 1) * 8;
    const float* Ag = A + (size_t)(bm + lrowA) * 2048 + lkA;
    const float* Wg = W + (size_t)(bn + tid) * 2048;
    uint32_t smem_base = smem_u32(smem);
    uint32_t As_s = smem_base + (lrowA * ST + lkA) * 4;
    uint32_t Bs_s = smem_base + (A_F + tid * ST) * 4;

    float acc[4][8][4];
#pragma unroll
    for (int mi = 0; mi < 4; mi++)
#pragma unroll
        for (int ni = 0; ni < 8; ni++)
#pragma unroll
            for (int t = 0; t < 4; t++) acc[mi][ni][t] = 0.0f;

    // prologue: stages 0..2
#pragma unroll
    for (int s = 0; s < 3; s++) {
        uint32_t ao = As_s + s * STAGE_F * 4;
        uint32_t bo = Bs_s + s * STAGE_F * 4;
        const float* ag = Ag + s * 16;
        const float* wg = Wg + s * 16;
        cp16(ao, ag); cp16(ao + 16, ag + 4);
        cp16(bo, wg); cp16(bo + 16, wg + 4);
        cp16(bo + 32, wg + 8); cp16(bo + 48, wg + 12);
        CP_COMMIT();
    }

    const int NKT = 128;
    for (int kt = 0; kt < NKT; kt++) {
        CP_WAIT2();
        __syncthreads();

        if (kt + 3 < NKT) {
            int s = (kt + 3) & 3;
            uint32_t ao = As_s + s * STAGE_F * 4;
            uint32_t bo = Bs_s + s * STAGE_F * 4;
            const float* ag = Ag + (kt + 3) * 16;
            const float* wg = Wg + (kt + 3) * 16;
            cp16(ao, ag); cp16(ao + 16, ag + 4);
            cp16(bo, wg); cp16(bo + 16, wg + 4);
            cp16(bo + 32, wg + 8); cp16(bo + 48, wg + 12);
        }
        CP_COMMIT();

        const float* Ab = smem + (kt & 3) * STAGE_F;
        const float* Bb = Ab + A_F;
#pragma unroll
        for (int ks = 0; ks < 2; ks++) {
            int k8 = ks * 8;
            uint32_t a[4][4], b[8][2];
#pragma unroll
            for (int mi = 0; mi < 4; mi++) {
                int m0 = wm + mi * 16 + gid;
                a[mi][0] = __float_as_uint(Ab[m0 * ST + k8 + tig]);
                a[mi][1] = __float_as_uint(Ab[(m0 + 8) * ST + k8 + tig]);
                a[mi][2] = __float_as_uint(Ab[m0 * ST + k8 + tig + 4]);
                a[mi][3] = __float_as_uint(Ab[(m0 + 8) * ST + k8 + tig + 4]);
            }
#pragma unroll
            for (int ni = 0; ni < 8; ni++) {
                int n0 = wn + ni * 8 + gid;
                b[ni][0] = __float_as_uint(Bb[n0 * ST + k8 + tig]);
                b[ni][1] = __float_as_uint(Bb[n0 * ST + k8 + tig + 4]);
            }
#pragma unroll
            for (int mi = 0; mi < 4; mi++)
#pragma unroll
                for (int ni = 0; ni < 8; ni++)
                    mma_tf32(acc[mi][ni], a[mi], b[ni]);
        }
    }

    // epilogue
#pragma unroll
    for (int mi = 0; mi < 4; mi++) {
#pragma unroll
        for (int ni = 0; ni < 8; ni++) {
            int row0 = bm + wm + mi * 16 + gid;
            int col = bn + wn + ni * 8 + tig * 2;
            *(float2*)(C + (size_t)row0 * 2048 + col) =
                make_float2(acc[mi][ni][0], acc[mi][ni][1]);
            *(float2*)(C + (size_t)(row0 + 8) * 2048 + col) =
                make_float2(acc[mi][ni][2], acc[mi][ni][3]);
        }
    }
}

// ---------------------------------------------------------------------------
// ttt_lr projection: out[t,h] = dot(H[t,:2048], Wlr[h,:2048]) + lr_bias[h]
// ---------------------------------------------------------------------------
__global__ __launch_bounds__(256) void lr_kernel(
    const float* __restrict__ H, const float* __restrict__ Wlr,
    const float* __restrict__ lr_bias, float* __restrict__ out)
{
    int warp = threadIdx.x >> 5, lane = threadIdx.x & 31;
    int t = blockIdx.x * 8 + warp;
    const float* hrow = H + (size_t)t * 2048;
    float acc[32];
#pragma unroll
    for (int h = 0; h < 32; h++) acc[h] = 0.0f;

    for (int c0 = lane * 4; c0 < 2048; c0 += 128) {
        float4 hv = *(const float4*)(hrow + c0);
#pragma unroll
        for (int h = 0; h < 32; h++) {
            float4 wv = *(const float4*)(Wlr + (size_t)h * 2048 + c0);
            acc[h] += hv.x * wv.x + hv.y * wv.y + hv.z * wv.z + hv.w * wv.w;
        }
    }
#pragma unroll
    for (int h = 0; h < 32; h++) {
        float v = acc[h];
        v += __shfl_xor_sync(0xffffffffu, v, 16);
        v += __shfl_xor_sync(0xffffffffu, v, 8);
        v += __shfl_xor_sync(0xffffffffu, v, 4);
        v += __shfl_xor_sync(0xffffffffu, v, 2);
        v += __shfl_xor_sync(0xffffffffu, v, 1);
        if (lane == h) out[(size_t)t * 32 + h] = v + lr_bias[h];
    }
}

// ---------------------------------------------------------------------------
// Scan kernel: one CTA per (b,h) pair, loops over 128 minibatches.
// ---------------------------------------------------------------------------
__device__ __forceinline__ float rsum16(float v)
{
    v += __shfl_xor_sync(0xffffffffu, v, 1);
    v += __shfl_xor_sync(0xffffffffu, v, 2);
    v += __shfl_xor_sync(0xffffffffu, v, 4);
    v += __shfl_xor_sync(0xffffffffu, v, 8);
    return v;
}

__global__ __launch_bounds__(256, 1) void scan_kernel(
    const float* __restrict__ Q, const float* __restrict__ K_,
    const float* __restrict__ V, const float* __restrict__ LR,
    const float* __restrict__ W1_0, const float* __restrict__ b1_0,
    const float* __restrict__ lnw, const float* __restrict__ lnb,
    const float* __restrict__ ltk, float* __restrict__ Y)
{
    const int SD = 65;
    __shared__ __align__(16) float W1[64 * 64];
    __shared__ float xq[16 * 65], xk[16 * 65], xv[16 * 65], gr[16 * 65];
    __shared__ float b1v[64], gam[64], bet[64];
    __shared__ float coef[256], evec[16], tok[16];

    int bh = blockIdx.x, b = bh >> 5, h = bh & 31;
    int tid = threadIdx.x;

    for (int i = tid; i < 4096; i += 256) W1[i] = W1_0[h * 4096 + i];
    if (tid < 64) {
        b1v[tid] = b1_0[h * 64 + tid];
        gam[tid] = lnw[h * 64 + tid];
        bet[tid] = lnb[h * 64 + tid];
    }
    if (tid < 16) tok[tid] = fmaxf(1.0f / (float)(tid + 1) + ltk[tid], 0.0f);
    __syncthreads();

    int r = tid >> 4;
    int g4 = (tid & 15) << 2;

    for (int nm = 0; nm < 128; nm++) {
        size_t base = ((size_t)b * 2048 + (size_t)nm * 16) * 2048 + (size_t)h * 64;
        for (int i = tid; i < 1024; i += 256) {
            int k = i >> 6, d = i & 63;
            size_t gi = base + (size_t)k * 2048 + d;
            xq[k * SD + d] = Q[gi];
            xk[k * SD + d] = K_[gi];
            xv[k * SD + d] = V[gi];
        }
        if (tid < 16) {
            float x = LR[((size_t)b * 2048 + (size_t)nm * 16 + tid) * 32 + h];
            evec[tid] = (1.0f / (1.0f + expf(-x))) * (1.0f / 64.0f);
        }
        __syncthreads();

        float z[4], qw[4];
#pragma unroll
        for (int t = 0; t < 4; t++) { z[t] = b1v[g4 + t]; qw[t] = b1v[g4 + t]; }
        for (int c = 0; c < 64; c++) {
            float kc = xk[r * SD + c], qc = xq[r * SD + c];
            float4 w4 = *(const float4*)&W1[c * 64 + g4];
            z[0] += kc * w4.x; z[1] += kc * w4.y; z[2] += kc * w4.z; z[3] += kc * w4.w;
            qw[0] += qc * w4.x; qw[1] += qc * w4.y; qw[2] += qc * w4.z; qw[3] += qc * w4.w;
        }

        float s = z[0] + z[1] + z[2] + z[3];
        s = rsum16(s);
        float mu = s * (1.0f / 64.0f);
        float xh[4]; float vs = 0.0f;
#pragma unroll
        for (int t = 0; t < 4; t++) { float d0 = z[t] - mu; xh[t] = d0; vs += d0 * d0; }
        vs = rsum16(vs);
        float rstd = 1.0f / sqrtf(vs * (1.0f / 64.0f) + 1e-6f);
        float gxh[4]; float s1 = 0.0f, s2 = 0.0f;
#pragma unroll
        for (int t = 0; t < 4; t++) {
            xh[t] *= rstd;
            float tgt = xv[r * SD + g4 + t] - xk[r * SD + g4 + t];
            float gm = gam[g4 + t];
            gxh[t] = (gm * xh[t] + bet[g4 + t] - tgt) * gm;
            s1 += gxh[t]; s2 += gxh[t] * xh[t];
        }
        s1 = rsum16(s1);
        s2 = rsum16(s2);
        float c1 = rstd * (1.0f / 64.0f);
#pragma unroll
        for (int t = 0; t < 4; t++)
            gr[r * SD + g4 + t] = (64.0f * gxh[t] - s1 - xh[t] * s2) * c1;
        __syncthreads();

        {
            int i = r, j = tid & 15;
            float a = 0.0f;
            for (int c = 0; c < 64; c++) a += xq[i * SD + c] * xk[j * SD + c];
            coef[i * 16 + j] = (j <= i) ? tok[i] * evec[j] * (1.0f + a) : 0.0f;
        }
        __syncthreads();

        float zb[4] = {qw[0], qw[1], qw[2], qw[3]};
        for (int j = 0; j < 16; j++) {
            float cf = coef[r * 16 + j];
            zb[0] -= cf * gr[j * SD + g4 + 0];
            zb[1] -= cf * gr[j * SD + g4 + 1];
            zb[2] -= cf * gr[j * SD + g4 + 2];
            zb[3] -= cf * gr[j * SD + g4 + 3];
        }
        float s0 = zb[0] + zb[1] + zb[2] + zb[3];
        s0 = rsum16(s0);
        float mu2 = s0 * (1.0f / 64.0f);
        float v2 = 0.0f;
#pragma unroll
        for (int t = 0; t < 4; t++) { float d0 = zb[t] - mu2; v2 += d0 * d0; }
        v2 = rsum16(v2);
        float rstd2 = rsqrtf(v2 * (1.0f / 64.0f) + 1e-6f);
        {
            float o0 = xq[r * SD + g4 + 0] + gam[g4 + 0] * ((zb[0] - mu2) * rstd2) + bet[g4 + 0];
            float o1 = xq[r * SD + g4 + 1] + gam[g4 + 1] * ((zb[1] - mu2) * rstd2) + bet[g4 + 1];
            float o2 = xq[r * SD + g4 + 2] + gam[g4 + 2] * ((zb[2] - mu2) * rstd2) + bet[g4 + 2];
            float o3 = xq[r * SD + g4 + 3] + gam[g4 + 3] * ((zb[3] - mu2) * rstd2) + bet[g4 + 3];
            *(float4*)&Y[base + (size_t)r * 2048 + g4] = make_float4(o0, o1, o2, o3);
        }
        __syncthreads();

        for (int i = tid; i < 1024; i += 256) {
            int j = i >> 6, d = i & 63;
            gr[j * SD + d] *= tok[15] * evec[j];
        }
        __syncthreads();

#pragma unroll
        for (int cc = 0; cc < 4; cc++) {
            int c = r + cc * 16;
            float4* wp = (float4*)&W1[c * 64 + g4];
            float4 w = *wp;
#pragma unroll
            for (int j = 0; j < 16; j++) {
                float xkc = xk[j * SD + c];
                w.x -= xkc * gr[j * SD + g4 + 0];
                w.y -= xkc * gr[j * SD + g4 + 1];
                w.z -= xkc * gr[j * SD + g4 + 2];
                w.w -= xkc * gr[j * SD + g4 + 3];
            }
            *wp = w;
        }
        if (tid < 64) {
            float bb = b1v[tid];
#pragma unroll
            for (int j = 0; j < 16; j++) bb -= gr[j * SD + tid];
            b1v[tid] = bb;
        }
        __syncthreads();
    }
}

// ---------------------------------------------------------------------------
// Post layernorm over HS=2048, in place on Y; output rounded to tf32 values
// (feeds the o-projection GEMM which assumes pre-rounded input).
// ---------------------------------------------------------------------------
__global__ void postln_kernel(float* __restrict__ Y,
                              const float* __restrict__ w, const float* __restrict__ b)
{
    int t = blockIdx.x;
    float* row = Y + (size_t)t * 2048;
    __shared__ float rs[8], rss[8], mv[2];
    int tid = threadIdx.x;
    float v[8]; float s = 0.0f, ss = 0.0f;
#pragma unroll
    for (int i = 0; i < 8; i++) {
        v[i] = row[tid + i * 256];
        s += v[i]; ss += v[i] * v[i];
    }
#pragma unroll
    for (int m = 16; m >= 1; m >>= 1) {
        s  += __shfl_xor_sync(0xffffffffu, s, m);
        ss += __shfl_xor_sync(0xffffffffu, ss, m);
    }
    if ((tid & 31) == 0) { rs[tid >> 5] = s; rss[tid >> 5] = ss; }
    __syncthreads();
    if (tid == 0) {
        float a = 0.0f, c = 0.0f;
        for (int i = 0; i < 8; i++) { a += rs[i]; c += rss[i]; }
        float mu = a * (1.0f / 2048.0f);
        float var = c * (1.0f / 2048.0f) - mu * mu;
        mv[0] = mu; mv[1] = rsqrtf(var + 1e-6f);
    }
    __syncthreads();
    float mu = mv[0], rstd = mv[1];
#pragma unroll
    for (int i = 0; i < 8; i++) {
        int d = tid + i * 256;
        float o = w[d] * ((v[i] - mu) * rstd) + b[d];
        row[d] = __uint_as_float(f2tf(o));
    }
}

// ---------------------------------------------------------------------------
extern "C" void kernel_launch(void* const* d_in, const int* in_sizes, int n_in,
                              void* d_out, int out_size)
{
    const float* hidden = (const float*)d_in[0];
    const float* q_w  = (const float*)d_in[2];
    const float* k_w  = (const float*)d_in[3];
    const float* v_w  = (const float*)d_in[4];
    const float* o_w  = (const float*)d_in[5];
    const float* W1_0 = (const float*)d_in[6];
    const float* b1_0 = (const float*)d_in[7];
    const float* lnw  = (const float*)d_in[8];
    const float* lnb  = (const float*)d_in[9];
    const float* lr_w = (const float*)d_in[10];
    const float* lr_b = (const float*)d_in[11];
    const float* ltk  = (const float*)d_in[12];
    const float* pnw  = (const float*)d_in[13];
    const float* pnb  = (const float*)d_in[14];
    float* out = (float*)d_out;

    float *Qp, *Kp, *Vp, *Yp, *LRp, *Hr, *Wq, *Wk, *Wv, *Wo;
    cudaGetSymbolAddress((void**)&Qp,  g_Q);
    cudaGetSymbolAddress((void**)&Kp,  g_K);
    cudaGetSymbolAddress((void**)&Vp,  g_V);
    cudaGetSymbolAddress((void**)&Yp,  g_Y);
    cudaGetSymbolAddress((void**)&LRp, g_LR);
    cudaGetSymbolAddress((void**)&Hr,  g_Hr);
    cudaGetSymbolAddress((void**)&Wq,  g_Wq);
    cudaGetSymbolAddress((void**)&Wk,  g_Wk);
    cudaGetSymbolAddress((void**)&Wv,  g_Wv);
    cudaGetSymbolAddress((void**)&Wo,  g_Wo);

    cudaFuncSetAttribute(gemm_tf32_nt, cudaFuncAttributeMaxDynamicSharedMemorySize, GEMM_SMEM);

    // pre-round all GEMM inputs to tf32 values (bit-identical to in-loop cvt)
    round_tf32_kernel<<<16384, 256>>>(hidden, Hr, 8192 * 2048 / 4);
    round_tf32_kernel<<<4096, 256>>>(q_w, Wq, 2048 * 2048 / 4);
    round_tf32_kernel<<<4096, 256>>>(k_w, Wk, 2048 * 2048 / 4);
    round_tf32_kernel<<<4096, 256>>>(v_w, Wv, 2048 * 2048 / 4);
    round_tf32_kernel<<<4096, 256>>>(o_w, Wo, 2048 * 2048 / 4);

    dim3 gg(2048 / 256, 8192 / 128);
    gemm_tf32_nt<<<gg, 256, GEMM_SMEM>>>(Hr, Wq, Qp);
    gemm_tf32_nt<<<gg, 256, GEMM_SMEM>>>(Hr, Wk, Kp);
    gemm_tf32_nt<<<gg, 256, GEMM_SMEM>>>(Hr, Wv, Vp);
    lr_kernel<<<1024, 256>>>(hidden, lr_w, lr_b, LRp);
    scan_kernel<<<128, 256>>>(Qp, Kp, Vp, LRp, W1_0, b1_0, lnw, lnb, ltk, Yp);
    postln_kernel<<<8192, 256>>>(Yp, pnw, pnb);
    gemm_tf32_nt<<<gg, 256, GEMM_SMEM>>>(Yp, Wo, out);
}

// round 10
// speedup vs baseline: 1.7097x; 1.7097x over previous
#include <cuda_runtime.h>
#include <cuda_fp16.h>
#include <math.h>
#include <stdint.h>

// Problem constants: B=4, L=2048, HS=2048, NH=32, HD=64, K=16, NM=128, M=B*L=8192

__device__ float g_Q[8192 * 2048];
__device__ float g_K[8192 * 2048];
__device__ float g_V[8192 * 2048];
__device__ float g_Y[8192 * 2048];
__device__ float g_LR[8192 * 32];
__device__ __half g_Hh[8192 * 2048];
__device__ __half g_Yh[8192 * 2048];
__device__ __half g_Wqh[2048 * 2048];
__device__ __half g_Wkh[2048 * 2048];
__device__ __half g_Wvh[2048 * 2048];
__device__ __half g_Woh[2048 * 2048];

// ---------------------------------------------------------------------------
__device__ __forceinline__ void mma_f16(float* c, const uint32_t* a, const uint32_t* b) {
    asm volatile(
        "mma.sync.aligned.m16n8k16.row.col.f32.f16.f16.f32 "
        "{%0,%1,%2,%3}, {%4,%5,%6,%7}, {%8,%9}, {%0,%1,%2,%3};"
        : "+f"(c[0]), "+f"(c[1]), "+f"(c[2]), "+f"(c[3])
        : "r"(a[0]), "r"(a[1]), "r"(a[2]), "r"(a[3]), "r"(b[0]), "r"(b[1]));
}

__device__ __forceinline__ uint32_t smem_u32(const void* p) {
    uint32_t a;
    asm("{ .reg .u64 t; cvta.to.shared.u64 t, %1; cvt.u32.u64 %0, t; }" : "=r"(a) : "l"(p));
    return a;
}

__device__ __forceinline__ void cp16(uint32_t s, const void* g) {
    asm volatile("cp.async.cg.shared.global [%0], [%1], 16;" :: "r"(s), "l"(g));
}
#define CP_COMMIT() asm volatile("cp.async.commit_group;" ::: "memory")
#define CP_WAIT1()  asm volatile("cp.async.wait_group 1;" ::: "memory")

// ---------------------------------------------------------------------------
// f32 -> f16 conversion (float4 -> 4 halves)
// ---------------------------------------------------------------------------
__global__ void cvt_f16_kernel(const float* __restrict__ in, __half* __restrict__ out, int n4)
{
    int i = blockIdx.x * blockDim.x + threadIdx.x;
    if (i < n4) {
        float4 v = ((const float4*)in)[i];
        __half2* o = (__half2*)(out + (size_t)i * 4);
        o[0] = __floats2half2_rn(v.x, v.y);
        o[1] = __floats2half2_rn(v.z, v.w);
    }
}

// ---------------------------------------------------------------------------
// FP16 tensor-core GEMM: C[m,n] = sum_k A[m,k]*W[n,k], fp32 accumulate.
// A: 8192x2048 half row-major, W: 2048x2048 half row-major.
// 128x128 CTA tile, 8 warps of 64x32, BK=32 (2 k16 slabs), 3-stage cp.async.
// Smem [row][k], row stride 40 halves (20 words, 80B): fragment LDS bank =
// (20*gid + tig (+4) (+8)) mod 32 — all 32 lanes distinct, conflict-free;
// 80B rows keep cp.async destinations 16B-aligned.
// ---------------------------------------------------------------------------
#define ST2 40                      // halves per smem row
#define A_HF (128 * ST2)            // halves per A stage (5120)
#define STAGE_HF (2 * A_HF)         // A+B per stage (10240 halves = 20480 B)
#define GEMM_SMEM (3 * STAGE_HF * 2)  // 61440 bytes

__global__ __launch_bounds__(256, 2) void gemm_f16_nt(
    const __half* __restrict__ A, const __half* __restrict__ W,
    float* __restrict__ C)
{
    extern __shared__ __align__(16) __half smh[];

    int tid = threadIdx.x;
    int bm = blockIdx.y * 128, bn = blockIdx.x * 128;
    int warp = tid >> 5, lane = tid & 31;
    int gid = lane >> 2, tig = lane & 3;
    int wm = (warp & 1) * 64, wn = (warp >> 1) * 32;

    // loaders: thread -> row tid>>1, 16-half segment (tid&1); 2 cp16 each for A and B
    int lrow = tid >> 1, lseg = (tid & 1) * 16;
    const __half* Ag = A + (size_t)(bm + lrow) * 2048 + lseg;
    const __half* Wg = W + (size_t)(bn + lrow) * 2048 + lseg;
    uint32_t base_s = smem_u32(smh);
    uint32_t As_s = base_s + (lrow * ST2 + lseg) * 2;
    uint32_t Bs_s = base_s + (A_HF + lrow * ST2 + lseg) * 2;

    float acc[4][4][4];
#pragma unroll
    for (int mi = 0; mi < 4; mi++)
#pragma unroll
        for (int ni = 0; ni < 4; ni++)
#pragma unroll
            for (int t = 0; t < 4; t++) acc[mi][ni][t] = 0.0f;

    // prologue: stages 0,1
#pragma unroll
    for (int s = 0; s < 2; s++) {
        uint32_t ao = As_s + s * STAGE_HF * 2;
        uint32_t bo = Bs_s + s * STAGE_HF * 2;
        const __half* ag = Ag + s * 32;
        const __half* wg = Wg + s * 32;
        cp16(ao, ag); cp16(ao + 16, ag + 8);
        cp16(bo, wg); cp16(bo + 16, wg + 8);
        CP_COMMIT();
    }

    const int NKT = 64;  // 2048 / 32
    for (int kt = 0; kt < NKT; kt++) {
        CP_WAIT1();
        __syncthreads();

        if (kt + 2 < NKT) {
            int s = (kt + 2) % 3;
            uint32_t ao = As_s + s * STAGE_HF * 2;
            uint32_t bo = Bs_s + s * STAGE_HF * 2;
            const __half* ag = Ag + (kt + 2) * 32;
            const __half* wg = Wg + (kt + 2) * 32;
            cp16(ao, ag); cp16(ao + 16, ag + 8);
            cp16(bo, wg); cp16(bo + 16, wg + 8);
        }
        CP_COMMIT();

        const uint32_t* Aw = (const uint32_t*)(smh + (kt % 3) * STAGE_HF);
        const uint32_t* Bw = (const uint32_t*)(smh + (kt % 3) * STAGE_HF + A_HF);
#pragma unroll
        for (int ks = 0; ks < 2; ks++) {
            int kb = ks * 8;  // word offset of k16 slab
            uint32_t a[4][4], b[4][2];
#pragma unroll
            for (int mi = 0; mi < 4; mi++) {
                int m0 = wm + mi * 16 + gid;
                a[mi][0] = Aw[m0 * 20 + kb + tig];
                a[mi][1] = Aw[(m0 + 8) * 20 + kb + tig];
                a[mi][2] = Aw[m0 * 20 + kb + tig + 4];
                a[mi][3] = Aw[(m0 + 8) * 20 + kb + tig + 4];
            }
#pragma unroll
            for (int ni = 0; ni < 4; ni++) {
                int n0 = wn + ni * 8 + gid;
                b[ni][0] = Bw[n0 * 20 + kb + tig];
                b[ni][1] = Bw[n0 * 20 + kb + tig + 4];
            }
#pragma unroll
            for (int mi = 0; mi < 4; mi++)
#pragma unroll
                for (int ni = 0; ni < 4; ni++)
                    mma_f16(acc[mi][ni], a[mi], b[ni]);
        }
    }

    // epilogue: c0,c1 at (gid, 2*tig..+1); c2,c3 at (gid+8, ...)
#pragma unroll
    for (int mi = 0; mi < 4; mi++) {
#pragma unroll
        for (int ni = 0; ni < 4; ni++) {
            int row0 = bm + wm + mi * 16 + gid;
            int col = bn + wn + ni * 8 + tig * 2;
            *(float2*)(C + (size_t)row0 * 2048 + col) =
                make_float2(acc[mi][ni][0], acc[mi][ni][1]);
            *(float2*)(C + (size_t)(row0 + 8) * 2048 + col) =
                make_float2(acc[mi][ni][2], acc[mi][ni][3]);
        }
    }
}

// ---------------------------------------------------------------------------
// ttt_lr projection: out[t,h] = dot(H[t,:2048], Wlr[h,:2048]) + lr_bias[h]
// ---------------------------------------------------------------------------
__global__ __launch_bounds__(256) void lr_kernel(
    const float* __restrict__ H, const float* __restrict__ Wlr,
    const float* __restrict__ lr_bias, float* __restrict__ out)
{
    int warp = threadIdx.x >> 5, lane = threadIdx.x & 31;
    int t = blockIdx.x * 8 + warp;
    const float* hrow = H + (size_t)t * 2048;
    float acc[32];
#pragma unroll
    for (int h = 0; h < 32; h++) acc[h] = 0.0f;

    for (int c0 = lane * 4; c0 < 2048; c0 += 128) {
        float4 hv = *(const float4*)(hrow + c0);
#pragma unroll
        for (int h = 0; h < 32; h++) {
            float4 wv = *(const float4*)(Wlr + (size_t)h * 2048 + c0);
            acc[h] += hv.x * wv.x + hv.y * wv.y + hv.z * wv.z + hv.w * wv.w;
        }
    }
#pragma unroll
    for (int h = 0; h < 32; h++) {
        float v = acc[h];
        v += __shfl_xor_sync(0xffffffffu, v, 16);
        v += __shfl_xor_sync(0xffffffffu, v, 8);
        v += __shfl_xor_sync(0xffffffffu, v, 4);
        v += __shfl_xor_sync(0xffffffffu, v, 2);
        v += __shfl_xor_sync(0xffffffffu, v, 1);
        if (lane == h) out[(size_t)t * 32 + h] = v + lr_bias[h];
    }
}

// ---------------------------------------------------------------------------
// Scan kernel: one CTA per (b,h) pair, loops over 128 minibatches.
// ---------------------------------------------------------------------------
__device__ __forceinline__ float rsum16(float v)
{
    v += __shfl_xor_sync(0xffffffffu, v, 1);
    v += __shfl_xor_sync(0xffffffffu, v, 2);
    v += __shfl_xor_sync(0xffffffffu, v, 4);
    v += __shfl_xor_sync(0xffffffffu, v, 8);
    return v;
}

__global__ __launch_bounds__(256, 1) void scan_kernel(
    const float* __restrict__ Q, const float* __restrict__ K_,
    const float* __restrict__ V, const float* __restrict__ LR,
    const float* __restrict__ W1_0, const float* __restrict__ b1_0,
    const float* __restrict__ lnw, const float* __restrict__ lnb,
    const float* __restrict__ ltk, float* __restrict__ Y)
{
    const int SD = 65;
    __shared__ __align__(16) float W1[64 * 64];
    __shared__ float xq[16 * 65], xk[16 * 65], xv[16 * 65], gr[16 * 65];
    __shared__ float b1v[64], gam[64], bet[64];
    __shared__ float coef[256], evec[16], tok[16];

    int bh = blockIdx.x, b = bh >> 5, h = bh & 31;
    int tid = threadIdx.x;

    for (int i = tid; i < 4096; i += 256) W1[i] = W1_0[h * 4096 + i];
    if (tid < 64) {
        b1v[tid] = b1_0[h * 64 + tid];
        gam[tid] = lnw[h * 64 + tid];
        bet[tid] = lnb[h * 64 + tid];
    }
    if (tid < 16) tok[tid] = fmaxf(1.0f / (float)(tid + 1) + ltk[tid], 0.0f);
    __syncthreads();

    int r = tid >> 4;
    int g4 = (tid & 15) << 2;

    for (int nm = 0; nm < 128; nm++) {
        size_t base = ((size_t)b * 2048 + (size_t)nm * 16) * 2048 + (size_t)h * 64;
        for (int i = tid; i < 1024; i += 256) {
            int k = i >> 6, d = i & 63;
            size_t gi = base + (size_t)k * 2048 + d;
            xq[k * SD + d] = Q[gi];
            xk[k * SD + d] = K_[gi];
            xv[k * SD + d] = V[gi];
        }
        if (tid < 16) {
            float x = LR[((size_t)b * 2048 + (size_t)nm * 16 + tid) * 32 + h];
            evec[tid] = (1.0f / (1.0f + expf(-x))) * (1.0f / 64.0f);
        }
        __syncthreads();

        float z[4], qw[4];
#pragma unroll
        for (int t = 0; t < 4; t++) { z[t] = b1v[g4 + t]; qw[t] = b1v[g4 + t]; }
        for (int c = 0; c < 64; c++) {
            float kc = xk[r * SD + c], qc = xq[r * SD + c];
            float4 w4 = *(const float4*)&W1[c * 64 + g4];
            z[0] += kc * w4.x; z[1] += kc * w4.y; z[2] += kc * w4.z; z[3] += kc * w4.w;
            qw[0] += qc * w4.x; qw[1] += qc * w4.y; qw[2] += qc * w4.z; qw[3] += qc * w4.w;
        }

        float s = z[0] + z[1] + z[2] + z[3];
        s = rsum16(s);
        float mu = s * (1.0f / 64.0f);
        float xh[4]; float vs = 0.0f;
#pragma unroll
        for (int t = 0; t < 4; t++) { float d0 = z[t] - mu; xh[t] = d0; vs += d0 * d0; }
        vs = rsum16(vs);
        float rstd = 1.0f / sqrtf(vs * (1.0f / 64.0f) + 1e-6f);
        float gxh[4]; float s1 = 0.0f, s2 = 0.0f;
#pragma unroll
        for (int t = 0; t < 4; t++) {
            xh[t] *= rstd;
            float tgt = xv[r * SD + g4 + t] - xk[r * SD + g4 + t];
            float gm = gam[g4 + t];
            gxh[t] = (gm * xh[t] + bet[g4 + t] - tgt) * gm;
            s1 += gxh[t]; s2 += gxh[t] * xh[t];
        }
        s1 = rsum16(s1);
        s2 = rsum16(s2);
        float c1 = rstd * (1.0f / 64.0f);
#pragma unroll
        for (int t = 0; t < 4; t++)
            gr[r * SD + g4 + t] = (64.0f * gxh[t] - s1 - xh[t] * s2) * c1;
        __syncthreads();

        {
            int i = r, j = tid & 15;
            float a = 0.0f;
            for (int c = 0; c < 64; c++) a += xq[i * SD + c] * xk[j * SD + c];
            coef[i * 16 + j] = (j <= i) ? tok[i] * evec[j] * (1.0f + a) : 0.0f;
        }
        __syncthreads();

        float zb[4] = {qw[0], qw[1], qw[2], qw[3]};
        for (int j = 0; j < 16; j++) {
            float cf = coef[r * 16 + j];
            zb[0] -= cf * gr[j * SD + g4 + 0];
            zb[1] -= cf * gr[j * SD + g4 + 1];
            zb[2] -= cf * gr[j * SD + g4 + 2];
            zb[3] -= cf * gr[j * SD + g4 + 3];
        }
        float s0 = zb[0] + zb[1] + zb[2] + zb[3];
        s0 = rsum16(s0);
        float mu2 = s0 * (1.0f / 64.0f);
        float v2 = 0.0f;
#pragma unroll
        for (int t = 0; t < 4; t++) { float d0 = zb[t] - mu2; v2 += d0 * d0; }
        v2 = rsum16(v2);
        float rstd2 = rsqrtf(v2 * (1.0f / 64.0f) + 1e-6f);
        {
            float o0 = xq[r * SD + g4 + 0] + gam[g4 + 0] * ((zb[0] - mu2) * rstd2) + bet[g4 + 0];
            float o1 = xq[r * SD + g4 + 1] + gam[g4 + 1] * ((zb[1] - mu2) * rstd2) + bet[g4 + 1];
            float o2 = xq[r * SD + g4 + 2] + gam[g4 + 2] * ((zb[2] - mu2) * rstd2) + bet[g4 + 2];
            float o3 = xq[r * SD + g4 + 3] + gam[g4 + 3] * ((zb[3] - mu2) * rstd2) + bet[g4 + 3];
            *(float4*)&Y[base + (size_t)r * 2048 + g4] = make_float4(o0, o1, o2, o3);
        }
        __syncthreads();

        for (int i = tid; i < 1024; i += 256) {
            int j = i >> 6, d = i & 63;
            gr[j * SD + d] *= tok[15] * evec[j];
        }
        __syncthreads();

#pragma unroll
        for (int cc = 0; cc < 4; cc++) {
            int c = r + cc * 16;
            float4* wp = (float4*)&W1[c * 64 + g4];
            float4 w = *wp;
#pragma unroll
            for (int j = 0; j < 16; j++) {
                float xkc = xk[j * SD + c];
                w.x -= xkc * gr[j * SD + g4 + 0];
                w.y -= xkc * gr[j * SD + g4 + 1];
                w.z -= xkc * gr[j * SD + g4 + 2];
                w.w -= xkc * gr[j * SD + g4 + 3];
            }
            *wp = w;
        }
        if (tid < 64) {
            float bb = b1v[tid];
#pragma unroll
            for (int j = 0; j < 16; j++) bb -= gr[j * SD + tid];
            b1v[tid] = bb;
        }
        __syncthreads();
    }
}

// ---------------------------------------------------------------------------
// Post layernorm over HS=2048; reads fp32 Y, writes fp16 Yh for the O-GEMM.
// ---------------------------------------------------------------------------
__global__ void postln_kernel(const float* __restrict__ Y, __half* __restrict__ Yh,
                              const float* __restrict__ w, const float* __restrict__ b)
{
    int t = blockIdx.x;
    const float* row = Y + (size_t)t * 2048;
    __half* rowh = Yh + (size_t)t * 2048;
    __shared__ float rs[8], rss[8], mv[2];
    int tid = threadIdx.x;
    float v[8]; float s = 0.0f, ss = 0.0f;
#pragma unroll
    for (int i = 0; i < 8; i++) {
        v[i] = row[tid + i * 256];
        s += v[i]; ss += v[i] * v[i];
    }
#pragma unroll
    for (int m = 16; m >= 1; m >>= 1) {
        s  += __shfl_xor_sync(0xffffffffu, s, m);
        ss += __shfl_xor_sync(0xffffffffu, ss, m);
    }
    if ((tid & 31) == 0) { rs[tid >> 5] = s; rss[tid >> 5] = ss; }
    __syncthreads();
    if (tid == 0) {
        float a = 0.0f, c = 0.0f;
        for (int i = 0; i < 8; i++) { a += rs[i]; c += rss[i]; }
        float mu = a * (1.0f / 2048.0f);
        float var = c * (1.0f / 2048.0f) - mu * mu;
        mv[0] = mu; mv[1] = rsqrtf(var + 1e-6f);
    }
    __syncthreads();
    float mu = mv[0], rstd = mv[1];
#pragma unroll
    for (int i = 0; i < 8; i++) {
        int d = tid + i * 256;
        float o = w[d] * ((v[i] - mu) * rstd) + b[d];
        rowh[d] = __float2half_rn(o);
    }
}

// ---------------------------------------------------------------------------
extern "C" void kernel_launch(void* const* d_in, const int* in_sizes, int n_in,
                              void* d_out, int out_size)
{
    const float* hidden = (const float*)d_in[0];
    const float* q_w  = (const float*)d_in[2];
    const float* k_w  = (const float*)d_in[3];
    const float* v_w  = (const float*)d_in[4];
    const float* o_w  = (const float*)d_in[5];
    const float* W1_0 = (const float*)d_in[6];
    const float* b1_0 = (const float*)d_in[7];
    const float* lnw  = (const float*)d_in[8];
    const float* lnb  = (const float*)d_in[9];
    const float* lr_w = (const float*)d_in[10];
    const float* lr_b = (const float*)d_in[11];
    const float* ltk  = (const float*)d_in[12];
    const float* pnw  = (const float*)d_in[13];
    const float* pnb  = (const float*)d_in[14];
    float* out = (float*)d_out;

    float *Qp, *Kp, *Vp, *Yp, *LRp;
    __half *Hh, *Yh, *Wqh, *Wkh, *Wvh, *Woh;
    cudaGetSymbolAddress((void**)&Qp,  g_Q);
    cudaGetSymbolAddress((void**)&Kp,  g_K);
    cudaGetSymbolAddress((void**)&Vp,  g_V);
    cudaGetSymbolAddress((void**)&Yp,  g_Y);
    cudaGetSymbolAddress((void**)&LRp, g_LR);
    cudaGetSymbolAddress((void**)&Hh,  g_Hh);
    cudaGetSymbolAddress((void**)&Yh,  g_Yh);
    cudaGetSymbolAddress((void**)&Wqh, g_Wqh);
    cudaGetSymbolAddress((void**)&Wkh, g_Wkh);
    cudaGetSymbolAddress((void**)&Wvh, g_Wvh);
    cudaGetSymbolAddress((void**)&Woh, g_Woh);

    cudaFuncSetAttribute(gemm_f16_nt, cudaFuncAttributeMaxDynamicSharedMemorySize, GEMM_SMEM);

    // convert GEMM inputs to fp16 (11-bit mantissa, same as tf32)
    cvt_f16_kernel<<<16384, 256>>>(hidden, Hh, 8192 * 2048 / 4);
    cvt_f16_kernel<<<4096, 256>>>(q_w, Wqh, 2048 * 2048 / 4);
    cvt_f16_kernel<<<4096, 256>>>(k_w, Wkh, 2048 * 2048 / 4);
    cvt_f16_kernel<<<4096, 256>>>(v_w, Wvh, 2048 * 2048 / 4);
    cvt_f16_kernel<<<4096, 256>>>(o_w, Woh, 2048 * 2048 / 4);

    dim3 gg(2048 / 128, 8192 / 128);
    gemm_f16_nt<<<gg, 256, GEMM_SMEM>>>(Hh, Wqh, Qp);
    gemm_f16_nt<<<gg, 256, GEMM_SMEM>>>(Hh, Wkh, Kp);
    gemm_f16_nt<<<gg, 256, GEMM_SMEM>>>(Hh, Wvh, Vp);
    lr_kernel<<<1024, 256>>>(hidden, lr_w, lr_b, LRp);
    scan_kernel<<<128, 256>>>(Qp, Kp, Vp, LRp, W1_0, b1_0, lnw, lnb, ltk, Yp);
    postln_kernel<<<8192, 256>>>(Yp, Yh, pnw, pnb);
    gemm_f16_nt<<<gg, 256, GEMM_SMEM>>>(Yh, Woh, out);
}

// round 11
// speedup vs baseline: 2.2841x; 1.3359x over previous
#include <cuda_runtime.h>
#include <cuda_fp16.h>
#include <math.h>
#include <stdint.h>

// Problem constants: B=4, L=2048, HS=2048, NH=32, HD=64, K=16, NM=128, M=B*L=8192

__device__ float g_Q[8192 * 2048];
__device__ float g_K[8192 * 2048];
__device__ float g_V[8192 * 2048];
__device__ float g_Y[8192 * 2048];
__device__ float g_LR[8192 * 32];
__device__ __half g_Hh[8192 * 2048];
__device__ __half g_Yh[8192 * 2048];
__device__ __half g_Wqh[2048 * 2048];
__device__ __half g_Wkh[2048 * 2048];
__device__ __half g_Wvh[2048 * 2048];
__device__ __half g_Woh[2048 * 2048];
__device__ __half g_Wlrh[32 * 2048];

// ---------------------------------------------------------------------------
__device__ __forceinline__ void mma_f16(float* c, const uint32_t* a, const uint32_t* b) {
    asm volatile(
        "mma.sync.aligned.m16n8k16.row.col.f32.f16.f16.f32 "
        "{%0,%1,%2,%3}, {%4,%5,%6,%7}, {%8,%9}, {%0,%1,%2,%3};"
        : "+f"(c[0]), "+f"(c[1]), "+f"(c[2]), "+f"(c[3])
        : "r"(a[0]), "r"(a[1]), "r"(a[2]), "r"(a[3]), "r"(b[0]), "r"(b[1]));
}

__device__ __forceinline__ uint32_t smem_u32(const void* p) {
    uint32_t a;
    asm("{ .reg .u64 t; cvta.to.shared.u64 t, %1; cvt.u32.u64 %0, t; }" : "=r"(a) : "l"(p));
    return a;
}

__device__ __forceinline__ void cp16(uint32_t s, const void* g) {
    asm volatile("cp.async.cg.shared.global [%0], [%1], 16;" :: "r"(s), "l"(g));
}
#define CP_COMMIT() asm volatile("cp.async.commit_group;" ::: "memory")
#define CP_WAIT1()  asm volatile("cp.async.wait_group 1;" ::: "memory")

// ---------------------------------------------------------------------------
// f32 -> f16 conversion (float4 -> 4 halves)
// ---------------------------------------------------------------------------
__global__ void cvt_f16_kernel(const float* __restrict__ in, __half* __restrict__ out, int n4)
{
    int i = blockIdx.x * blockDim.x + threadIdx.x;
    if (i < n4) {
        float4 v = ((const float4*)in)[i];
        __half2* o = (__half2*)(out + (size_t)i * 4);
        o[0] = __floats2half2_rn(v.x, v.y);
        o[1] = __floats2half2_rn(v.z, v.w);
    }
}

// ---------------------------------------------------------------------------
// FP16 tensor-core GEMM (round-10, proven): C[m,n] = sum_k A[m,k]*W[n,k].
// 128x128 CTA tile, 8 warps of 64x32, BK=32, 3-stage cp.async, occ 2.
// ---------------------------------------------------------------------------
#define ST2 40
#define A_HF (128 * ST2)
#define STAGE_HF (2 * A_HF)
#define GEMM_SMEM (3 * STAGE_HF * 2)

__global__ __launch_bounds__(256, 2) void gemm_f16_nt(
    const __half* __restrict__ A, const __half* __restrict__ W,
    float* __restrict__ C)
{
    extern __shared__ __align__(16) __half smh[];

    int tid = threadIdx.x;
    int bm = blockIdx.y * 128, bn = blockIdx.x * 128;
    int warp = tid >> 5, lane = tid & 31;
    int gid = lane >> 2, tig = lane & 3;
    int wm = (warp & 1) * 64, wn = (warp >> 1) * 32;

    int lrow = tid >> 1, lseg = (tid & 1) * 16;
    const __half* Ag = A + (size_t)(bm + lrow) * 2048 + lseg;
    const __half* Wg = W + (size_t)(bn + lrow) * 2048 + lseg;
    uint32_t base_s = smem_u32(smh);
    uint32_t As_s = base_s + (lrow * ST2 + lseg) * 2;
    uint32_t Bs_s = base_s + (A_HF + lrow * ST2 + lseg) * 2;

    float acc[4][4][4];
#pragma unroll
    for (int mi = 0; mi < 4; mi++)
#pragma unroll
        for (int ni = 0; ni < 4; ni++)
#pragma unroll
            for (int t = 0; t < 4; t++) acc[mi][ni][t] = 0.0f;

#pragma unroll
    for (int s = 0; s < 2; s++) {
        uint32_t ao = As_s + s * STAGE_HF * 2;
        uint32_t bo = Bs_s + s * STAGE_HF * 2;
        const __half* ag = Ag + s * 32;
        const __half* wg = Wg + s * 32;
        cp16(ao, ag); cp16(ao + 16, ag + 8);
        cp16(bo, wg); cp16(bo + 16, wg + 8);
        CP_COMMIT();
    }

    const int NKT = 64;
    for (int kt = 0; kt < NKT; kt++) {
        CP_WAIT1();
        __syncthreads();

        if (kt + 2 < NKT) {
            int s = (kt + 2) % 3;
            uint32_t ao = As_s + s * STAGE_HF * 2;
            uint32_t bo = Bs_s + s * STAGE_HF * 2;
            const __half* ag = Ag + (kt + 2) * 32;
            const __half* wg = Wg + (kt + 2) * 32;
            cp16(ao, ag); cp16(ao + 16, ag + 8);
            cp16(bo, wg); cp16(bo + 16, wg + 8);
        }
        CP_COMMIT();

        const uint32_t* Aw = (const uint32_t*)(smh + (kt % 3) * STAGE_HF);
        const uint32_t* Bw = (const uint32_t*)(smh + (kt % 3) * STAGE_HF + A_HF);
#pragma unroll
        for (int ks = 0; ks < 2; ks++) {
            int kb = ks * 8;
            uint32_t a[4][4], b[4][2];
#pragma unroll
            for (int mi = 0; mi < 4; mi++) {
                int m0 = wm + mi * 16 + gid;
                a[mi][0] = Aw[m0 * 20 + kb + tig];
                a[mi][1] = Aw[(m0 + 8) * 20 + kb + tig];
                a[mi][2] = Aw[m0 * 20 + kb + tig + 4];
                a[mi][3] = Aw[(m0 + 8) * 20 + kb + tig + 4];
            }
#pragma unroll
            for (int ni = 0; ni < 4; ni++) {
                int n0 = wn + ni * 8 + gid;
                b[ni][0] = Bw[n0 * 20 + kb + tig];
                b[ni][1] = Bw[n0 * 20 + kb + tig + 4];
            }
#pragma unroll
            for (int mi = 0; mi < 4; mi++)
#pragma unroll
                for (int ni = 0; ni < 4; ni++)
                    mma_f16(acc[mi][ni], a[mi], b[ni]);
        }
    }

#pragma unroll
    for (int mi = 0; mi < 4; mi++) {
#pragma unroll
        for (int ni = 0; ni < 4; ni++) {
            int row0 = bm + wm + mi * 16 + gid;
            int col = bn + wn + ni * 8 + tig * 2;
            *(float2*)(C + (size_t)row0 * 2048 + col) =
                make_float2(acc[mi][ni][0], acc[mi][ni][1]);
            *(float2*)(C + (size_t)(row0 + 8) * 2048 + col) =
                make_float2(acc[mi][ni][2], acc[mi][ni][3]);
        }
    }
}

// ---------------------------------------------------------------------------
// lr projection via fp16 MMA: LR[t,h] = dot(Hh[t,:], Wlr[h,:]) + lr_bias[h].
// M tile 128, N=32 fixed. 256 threads, 8 warps of 16x32 each. BK=32, 3-stage.
// ---------------------------------------------------------------------------
#define LR_A_HF (128 * 40)
#define LR_B_HF (32 * 40)
#define LR_STAGE (LR_A_HF + LR_B_HF)

__global__ __launch_bounds__(256, 1) void lr_mma_kernel(
    const __half* __restrict__ A, const __half* __restrict__ Wlr,
    const float* __restrict__ lr_bias, float* __restrict__ out)
{
    __shared__ __align__(16) __half smh[3 * LR_STAGE];

    int tid = threadIdx.x;
    int bm = blockIdx.x * 128;
    int warp = tid >> 5, lane = tid & 31;
    int gid = lane >> 2, tig = lane & 3;

    int lrow = tid >> 1, lseg = (tid & 1) * 16;
    const __half* Ag = A + (size_t)(bm + lrow) * 2048 + lseg;
    uint32_t base_s = smem_u32(smh);
    uint32_t As_s = base_s + (lrow * 40 + lseg) * 2;
    int brow = (tid & 63) >> 1, bseg2 = (tid & 1) * 16;
    const __half* Bg = Wlr + (size_t)brow * 2048 + bseg2;
    uint32_t Bs_s = base_s + (LR_A_HF + brow * 40 + bseg2) * 2;

    float acc[4][4];
#pragma unroll
    for (int ni = 0; ni < 4; ni++)
#pragma unroll
        for (int t = 0; t < 4; t++) acc[ni][t] = 0.0f;

#pragma unroll
    for (int s = 0; s < 2; s++) {
        uint32_t ao = As_s + s * LR_STAGE * 2;
        const __half* ag = Ag + s * 32;
        cp16(ao, ag); cp16(ao + 16, ag + 8);
        if (tid < 64) {
            uint32_t bo = Bs_s + s * LR_STAGE * 2;
            const __half* bg = Bg + s * 32;
            cp16(bo, bg); cp16(bo + 16, bg + 8);
        }
        CP_COMMIT();
    }

    const int NKT = 64;
    for (int kt = 0; kt < NKT; kt++) {
        CP_WAIT1();
        __syncthreads();

        if (kt + 2 < NKT) {
            int s = (kt + 2) % 3;
            uint32_t ao = As_s + s * LR_STAGE * 2;
            const __half* ag = Ag + (kt + 2) * 32;
            cp16(ao, ag); cp16(ao + 16, ag + 8);
            if (tid < 64) {
                uint32_t bo = Bs_s + s * LR_STAGE * 2;
                const __half* bg = Bg + (kt + 2) * 32;
                cp16(bo, bg); cp16(bo + 16, bg + 8);
            }
        }
        CP_COMMIT();

        const uint32_t* Aw = (const uint32_t*)(smh + (kt % 3) * LR_STAGE);
        const uint32_t* Bw = (const uint32_t*)(smh + (kt % 3) * LR_STAGE + LR_A_HF);
#pragma unroll
        for (int ks = 0; ks < 2; ks++) {
            int kb = ks * 8;
            uint32_t a[4], b[4][2];
            int m0 = warp * 16 + gid;
            a[0] = Aw[m0 * 20 + kb + tig];
            a[1] = Aw[(m0 + 8) * 20 + kb + tig];
            a[2] = Aw[m0 * 20 + kb + tig + 4];
            a[3] = Aw[(m0 + 8) * 20 + kb + tig + 4];
#pragma unroll
            for (int ni = 0; ni < 4; ni++) {
                int n0 = ni * 8 + gid;
                b[ni][0] = Bw[n0 * 20 + kb + tig];
                b[ni][1] = Bw[n0 * 20 + kb + tig + 4];
            }
#pragma unroll
            for (int ni = 0; ni < 4; ni++)
                mma_f16(acc[ni], a, b[ni]);
        }
    }

#pragma unroll
    for (int ni = 0; ni < 4; ni++) {
        int row0 = bm + warp * 16 + gid;
        int col = ni * 8 + tig * 2;
        float b0 = lr_bias[col], b1 = lr_bias[col + 1];
        *(float2*)(out + (size_t)row0 * 32 + col) =
            make_float2(acc[ni][0] + b0, acc[ni][1] + b1);
        *(float2*)(out + (size_t)(row0 + 8) * 32 + col) =
            make_float2(acc[ni][2] + b0, acc[ni][3] + b1);
    }
}

// ---------------------------------------------------------------------------
// Scan kernel: one CTA per (b,h), 128 serial minibatches.
// Double-buffered cp.async prefetch of xq/xk/xv; 3 barriers/iter;
// scale-pass folded into W1/b1 update; coef via float4 (SD=68).
// ---------------------------------------------------------------------------
__device__ __forceinline__ float rsum16(float v)
{
    v += __shfl_xor_sync(0xffffffffu, v, 1);
    v += __shfl_xor_sync(0xffffffffu, v, 2);
    v += __shfl_xor_sync(0xffffffffu, v, 4);
    v += __shfl_xor_sync(0xffffffffu, v, 8);
    return v;
}

#define SSD 68
#define TILE68 (16 * SSD)           // 1088 floats
#define SCAN_SMEM (2 * 3 * TILE68 * 4)  // 26112 bytes dynamic

__global__ __launch_bounds__(256, 1) void scan_kernel(
    const float* __restrict__ Q, const float* __restrict__ K_,
    const float* __restrict__ V, const float* __restrict__ LR,
    const float* __restrict__ W1_0, const float* __restrict__ b1_0,
    const float* __restrict__ lnw, const float* __restrict__ lnb,
    const float* __restrict__ ltk, float* __restrict__ Y)
{
    extern __shared__ __align__(16) float dsm[];   // [2][3][TILE68]
    __shared__ __align__(16) float W1[64 * 64];
    __shared__ __align__(16) float gr[TILE68];
    __shared__ float b1v[64], gam[64], bet[64];
    __shared__ float coef[256], evec[2][16], tok[16];

    int bh = blockIdx.x, b = bh >> 5, h = bh & 31;
    int tid = threadIdx.x;

    for (int i = tid; i < 4096; i += 256) W1[i] = W1_0[h * 4096 + i];
    if (tid < 64) {
        b1v[tid] = b1_0[h * 64 + tid];
        gam[tid] = lnw[h * 64 + tid];
        bet[tid] = lnb[h * 64 + tid];
    }
    if (tid < 16) tok[tid] = fmaxf(1.0f / (float)(tid + 1) + ltk[tid], 0.0f);

    int r = tid >> 4;
    int g4 = (tid & 15) << 2;
    int lk = tid >> 4, ld4 = (tid & 15) << 2;   // loader: row lk, quad ld4

    uint32_t dsm_s = smem_u32(dsm);
    size_t row_off = (size_t)lk * 2048 + ld4;
    size_t bb2048 = (size_t)b * 2048;

    // prologue: prefetch minibatch 0 into buffer 0
    {
        size_t gi = (bb2048) * 2048 + (size_t)h * 64 + row_off;
        uint32_t d0 = dsm_s + (lk * SSD + ld4) * 4;
        cp16(d0, Q + gi);
        cp16(d0 + TILE68 * 4, K_ + gi);
        cp16(d0 + 2 * TILE68 * 4, V + gi);
        CP_COMMIT();
    }
    float lrx = 0.0f;
    if (tid < 16) lrx = LR[(bb2048 + tid) * 32 + h];
    __syncthreads();

    for (int nm = 0; nm < 128; nm++) {
        int buf = nm & 1;
        // sigmoid for this minibatch (lrx prefetched last iter)
        if (tid < 16)
            evec[buf][tid] = (1.0f / (1.0f + expf(-lrx))) * (1.0f / 64.0f);

        // prefetch next minibatch into other buffer
        if (nm + 1 < 128) {
            size_t gi = (bb2048 + (size_t)(nm + 1) * 16) * 2048 + (size_t)h * 64 + row_off;
            uint32_t d0 = dsm_s + ((buf ^ 1) * 3 * TILE68 + lk * SSD + ld4) * 4;
            cp16(d0, Q + gi);
            cp16(d0 + TILE68 * 4, K_ + gi);
            cp16(d0 + 2 * TILE68 * 4, V + gi);
        }
        CP_COMMIT();
        CP_WAIT1();          // current buffer complete
        __syncthreads();     // sync1: evec + tiles visible

        if (tid < 16 && nm + 1 < 128)
            lrx = LR[(bb2048 + (size_t)(nm + 1) * 16 + tid) * 32 + h];

        const float* xq = dsm + buf * 3 * TILE68;
        const float* xk = xq + TILE68;
        const float* xv = xk + TILE68;

        // ---- phase 1: Z1/qW, grad, coef ----
        float z[4], qw[4];
#pragma unroll
        for (int t = 0; t < 4; t++) { z[t] = b1v[g4 + t]; qw[t] = b1v[g4 + t]; }
        for (int c = 0; c < 64; c++) {
            float kc = xk[r * SSD + c], qc = xq[r * SSD + c];
            float4 w4 = *(const float4*)&W1[c * 64 + g4];
            z[0] += kc * w4.x; z[1] += kc * w4.y; z[2] += kc * w4.z; z[3] += kc * w4.w;
            qw[0] += qc * w4.x; qw[1] += qc * w4.y; qw[2] += qc * w4.z; qw[3] += qc * w4.w;
        }

        float s = z[0] + z[1] + z[2] + z[3];
        s = rsum16(s);
        float mu = s * (1.0f / 64.0f);
        float xh[4]; float vs = 0.0f;
#pragma unroll
        for (int t = 0; t < 4; t++) { float d0 = z[t] - mu; xh[t] = d0; vs += d0 * d0; }
        vs = rsum16(vs);
        float rstd = 1.0f / sqrtf(vs * (1.0f / 64.0f) + 1e-6f);
        float gxh[4]; float s1 = 0.0f, s2 = 0.0f;
#pragma unroll
        for (int t = 0; t < 4; t++) {
            xh[t] *= rstd;
            float tgt = xv[r * SSD + g4 + t] - xk[r * SSD + g4 + t];
            float gm = gam[g4 + t];
            gxh[t] = (gm * xh[t] + bet[g4 + t] - tgt) * gm;
            s1 += gxh[t]; s2 += gxh[t] * xh[t];
        }
        s1 = rsum16(s1);
        s2 = rsum16(s2);
        float c1 = rstd * (1.0f / 64.0f);
#pragma unroll
        for (int t = 0; t < 4; t++)
            gr[r * SSD + g4 + t] = (64.0f * gxh[t] - s1 - xh[t] * s2) * c1;

        // coef[i,j] (independent of gr — same phase)
        {
            int i = r, j = tid & 15;
            const float4* xqv = (const float4*)(xq + i * SSD);
            const float4* xkv = (const float4*)(xk + j * SSD);
            float a = 0.0f;
#pragma unroll
            for (int c4 = 0; c4 < 16; c4++) {
                float4 qa = xqv[c4], kb = xkv[c4];
                a += qa.x * kb.x + qa.y * kb.y + qa.z * kb.z + qa.w * kb.w;
            }
            coef[i * 16 + j] = (j <= i) ? tok[i] * evec[buf][j] * (1.0f + a) : 0.0f;
        }
        __syncthreads();     // sync2

        // ---- phase 2: Z1_bar + output, W1/b1 update ----
        float zb[4] = {qw[0], qw[1], qw[2], qw[3]};
        for (int j = 0; j < 16; j++) {
            float cf = coef[r * 16 + j];
            float4 g = *(const float4*)&gr[j * SSD + g4];
            zb[0] -= cf * g.x; zb[1] -= cf * g.y; zb[2] -= cf * g.z; zb[3] -= cf * g.w;
        }
        float s0 = zb[0] + zb[1] + zb[2] + zb[3];
        s0 = rsum16(s0);
        float mu2 = s0 * (1.0f / 64.0f);
        float v2 = 0.0f;
#pragma unroll
        for (int t = 0; t < 4; t++) { float d0 = zb[t] - mu2; v2 += d0 * d0; }
        v2 = rsum16(v2);
        float rstd2 = rsqrtf(v2 * (1.0f / 64.0f) + 1e-6f);
        {
            size_t obase = (bb2048 + (size_t)nm * 16) * 2048 + (size_t)h * 64;
            float o0 = xq[r * SSD + g4 + 0] + gam[g4 + 0] * ((zb[0] - mu2) * rstd2) + bet[g4 + 0];
            float o1 = xq[r * SSD + g4 + 1] + gam[g4 + 1] * ((zb[1] - mu2) * rstd2) + bet[g4 + 1];
            float o2 = xq[r * SSD + g4 + 2] + gam[g4 + 2] * ((zb[2] - mu2) * rstd2) + bet[g4 + 2];
            float o3 = xq[r * SSD + g4 + 3] + gam[g4 + 3] * ((zb[3] - mu2) * rstd2) + bet[g4 + 3];
            *(float4*)&Y[obase + (size_t)r * 2048 + g4] = make_float4(o0, o1, o2, o3);
        }

        // W1 -= (last_eta*xk)^T @ gr  (scale folded in; j outer, gr loaded once)
        {
            float tok15 = tok[15];
            float4 w0 = *(float4*)&W1[(r + 0) * 64 + g4];
            float4 w1 = *(float4*)&W1[(r + 16) * 64 + g4];
            float4 w2 = *(float4*)&W1[(r + 32) * 64 + g4];
            float4 w3 = *(float4*)&W1[(r + 48) * 64 + g4];
#pragma unroll
            for (int j = 0; j < 16; j++) {
                float le = tok15 * evec[buf][j];
                float4 g = *(const float4*)&gr[j * SSD + g4];
                g.x *= le; g.y *= le; g.z *= le; g.w *= le;
                float k0 = xk[j * SSD + r];
                float k1 = xk[j * SSD + r + 16];
                float k2 = xk[j * SSD + r + 32];
                float k3 = xk[j * SSD + r + 48];
                w0.x -= k0 * g.x; w0.y -= k0 * g.y; w0.z -= k0 * g.z; w0.w -= k0 * g.w;
                w1.x -= k1 * g.x; w1.y -= k1 * g.y; w1.z -= k1 * g.z; w1.w -= k1 * g.w;
                w2.x -= k2 * g.x; w2.y -= k2 * g.y; w2.z -= k2 * g.z; w2.w -= k2 * g.w;
                w3.x -= k3 * g.x; w3.y -= k3 * g.y; w3.z -= k3 * g.z; w3.w -= k3 * g.w;
            }
            *(float4*)&W1[(r + 0) * 64 + g4] = w0;
            *(float4*)&W1[(r + 16) * 64 + g4] = w1;
            *(float4*)&W1[(r + 32) * 64 + g4] = w2;
            *(float4*)&W1[(r + 48) * 64 + g4] = w3;
        }
        if (tid < 64) {
            float tok15 = tok[15];
            float bb = b1v[tid];
#pragma unroll
            for (int j = 0; j < 16; j++)
                bb -= (tok15 * evec[buf][j]) * gr[j * SSD + tid];
            b1v[tid] = bb;
        }
        __syncthreads();     // sync3
    }
}

// ---------------------------------------------------------------------------
// Post layernorm over HS=2048; reads fp32 Y, writes fp16 Yh for the O-GEMM.
// ---------------------------------------------------------------------------
__global__ void postln_kernel(const float* __restrict__ Y, __half* __restrict__ Yh,
                              const float* __restrict__ w, const float* __restrict__ b)
{
    int t = blockIdx.x;
    const float* row = Y + (size_t)t * 2048;
    __half* rowh = Yh + (size_t)t * 2048;
    __shared__ float rs[8], rss[8], mv[2];
    int tid = threadIdx.x;
    float v[8]; float s = 0.0f, ss = 0.0f;
#pragma unroll
    for (int i = 0; i < 8; i++) {
        v[i] = row[tid + i * 256];
        s += v[i]; ss += v[i] * v[i];
    }
#pragma unroll
    for (int m = 16; m >= 1; m >>= 1) {
        s  += __shfl_xor_sync(0xffffffffu, s, m);
        ss += __shfl_xor_sync(0xffffffffu, ss, m);
    }
    if ((tid & 31) == 0) { rs[tid >> 5] = s; rss[tid >> 5] = ss; }
    __syncthreads();
    if (tid == 0) {
        float a = 0.0f, c = 0.0f;
        for (int i = 0; i < 8; i++) { a += rs[i]; c += rss[i]; }
        float mu = a * (1.0f / 2048.0f);
        float var = c * (1.0f / 2048.0f) - mu * mu;
        mv[0] = mu; mv[1] = rsqrtf(var + 1e-6f);
    }
    __syncthreads();
    float mu = mv[0], rstd = mv[1];
#pragma unroll
    for (int i = 0; i < 8; i++) {
        int d = tid + i * 256;
        float o = w[d] * ((v[i] - mu) * rstd) + b[d];
        rowh[d] = __float2half_rn(o);
    }
}

// ---------------------------------------------------------------------------
extern "C" void kernel_launch(void* const* d_in, const int* in_sizes, int n_in,
                              void* d_out, int out_size)
{
    const float* hidden = (const float*)d_in[0];
    const float* q_w  = (const float*)d_in[2];
    const float* k_w  = (const float*)d_in[3];
    const float* v_w  = (const float*)d_in[4];
    const float* o_w  = (const float*)d_in[5];
    const float* W1_0 = (const float*)d_in[6];
    const float* b1_0 = (const float*)d_in[7];
    const float* lnw  = (const float*)d_in[8];
    const float* lnb  = (const float*)d_in[9];
    const float* lr_w = (const float*)d_in[10];
    const float* lr_b = (const float*)d_in[11];
    const float* ltk  = (const float*)d_in[12];
    const float* pnw  = (const float*)d_in[13];
    const float* pnb  = (const float*)d_in[14];
    float* out = (float*)d_out;

    float *Qp, *Kp, *Vp, *Yp, *LRp;
    __half *Hh, *Yh, *Wqh, *Wkh, *Wvh, *Woh, *Wlrh;
    cudaGetSymbolAddress((void**)&Qp,  g_Q);
    cudaGetSymbolAddress((void**)&Kp,  g_K);
    cudaGetSymbolAddress((void**)&Vp,  g_V);
    cudaGetSymbolAddress((void**)&Yp,  g_Y);
    cudaGetSymbolAddress((void**)&LRp, g_LR);
    cudaGetSymbolAddress((void**)&Hh,  g_Hh);
    cudaGetSymbolAddress((void**)&Yh,  g_Yh);
    cudaGetSymbolAddress((void**)&Wqh, g_Wqh);
    cudaGetSymbolAddress((void**)&Wkh, g_Wkh);
    cudaGetSymbolAddress((void**)&Wvh, g_Wvh);
    cudaGetSymbolAddress((void**)&Woh, g_Woh);
    cudaGetSymbolAddress((void**)&Wlrh, g_Wlrh);

    cudaFuncSetAttribute(gemm_f16_nt, cudaFuncAttributeMaxDynamicSharedMemorySize, GEMM_SMEM);
    cudaFuncSetAttribute(scan_kernel, cudaFuncAttributeMaxDynamicSharedMemorySize, SCAN_SMEM);

    cvt_f16_kernel<<<16384, 256>>>(hidden, Hh, 8192 * 2048 / 4);
    cvt_f16_kernel<<<4096, 256>>>(q_w, Wqh, 2048 * 2048 / 4);
    cvt_f16_kernel<<<4096, 256>>>(k_w, Wkh, 2048 * 2048 / 4);
    cvt_f16_kernel<<<4096, 256>>>(v_w, Wvh, 2048 * 2048 / 4);
    cvt_f16_kernel<<<4096, 256>>>(o_w, Woh, 2048 * 2048 / 4);
    cvt_f16_kernel<<<64, 256>>>(lr_w, Wlrh, 32 * 2048 / 4);

    dim3 gg(2048 / 128, 8192 / 128);
    gemm_f16_nt<<<gg, 256, GEMM_SMEM>>>(Hh, Wqh, Qp);
    gemm_f16_nt<<<gg, 256, GEMM_SMEM>>>(Hh, Wkh, Kp);
    gemm_f16_nt<<<gg, 256, GEMM_SMEM>>>(Hh, Wvh, Vp);
    lr_mma_kernel<<<64, 256>>>(Hh, Wlrh, lr_b, LRp);
    scan_kernel<<<128, 256, SCAN_SMEM>>>(Qp, Kp, Vp, LRp, W1_0, b1_0, lnw, lnb, ltk, Yp);
    postln_kernel<<<8192, 256>>>(Yp, Yh, pnw, pnb);
    gemm_f16_nt<<<gg, 256, GEMM_SMEM>>>(Yh, Woh, out);
}